// round 4
// baseline (speedup 1.0000x reference)
#include <cuda_runtime.h>
#include <cstdint>

#define NLVL 16
#define TSZ (1 << 19)
#define TMASK ((1u << 19) - 1u)
#define PRIME_Y 2654435761u
#define PRIME_Z 805459861u

#define BMAX (1 << 20)          // BSZ = 1048576
#define NBINS (1 << 18)         // 64^3 morton bins
#define NCHUNK (NBINS / 1024)   // 256

// ---- scratch (device globals; no allocation allowed) ----
__device__ uint32_t g_hist[NBINS];   // histogram -> scanned offsets -> scatter cursors
__device__ uint32_t g_chunk[NCHUNK]; // chunk totals -> exclusive scanned
__device__ float4   g_pts[BMAX];     // sorted (p0,p1,p2, bitcast(orig idx))

// floor(16 * 2^(i/3)); ambiguous i=3,6,9,12,15 -> power-of-two branch
// (validated rel_err 3.9e-8).
__constant__ int c_res[NLVL] = {16, 20, 25, 32, 40, 50, 64, 80,
                                101, 128, 161, 203, 256, 322, 406, 512};

__device__ __forceinline__ uint32_t spread3(uint32_t v) {
    v &= 0x3FFu;
    v = (v | (v << 16)) & 0x030000FFu;
    v = (v | (v << 8))  & 0x0300F00Fu;
    v = (v | (v << 4))  & 0x030C30C3u;
    v = (v | (v << 2))  & 0x09249249u;
    return v;
}

__device__ __forceinline__ uint32_t morton64(float p0, float p1, float p2) {
    uint32_t c0 = (uint32_t)fminf(fmaxf(floorf((p0 + 1.0f) * 32.0f), 0.0f), 63.0f);
    uint32_t c1 = (uint32_t)fminf(fmaxf(floorf((p1 + 1.0f) * 32.0f), 0.0f), 63.0f);
    uint32_t c2 = (uint32_t)fminf(fmaxf(floorf((p2 + 1.0f) * 32.0f), 0.0f), 63.0f);
    return spread3(c0) | (spread3(c1) << 1) | (spread3(c2) << 2);
}

// ---- K1: histogram ----
__global__ void k_hist(const float* __restrict__ x, int B) {
    int b = blockIdx.x * blockDim.x + threadIdx.x;
    if (b >= B) return;
    atomicAdd(&g_hist[morton64(x[3 * b], x[3 * b + 1], x[3 * b + 2])], 1u);
}

// ---- K2: per-1024-bin chunk exclusive scan (in place) + chunk totals ----
__global__ void k_scan_chunks() {
    __shared__ uint32_t s[1024];
    const int t = threadIdx.x;
    const int base = blockIdx.x * 1024;
    const uint32_t v = g_hist[base + t];
    s[t] = v;
    __syncthreads();
    #pragma unroll
    for (int o = 1; o < 1024; o <<= 1) {
        uint32_t u = (t >= o) ? s[t - o] : 0u;
        __syncthreads();
        s[t] += u;
        __syncthreads();
    }
    g_hist[base + t] = s[t] - v;                 // exclusive within chunk
    if (t == 1023) g_chunk[blockIdx.x] = s[1023];
}

// ---- K3: exclusive scan of the 256 chunk totals ----
__global__ void k_scan_top() {
    __shared__ uint32_t s[NCHUNK];
    const int t = threadIdx.x;
    const uint32_t v = g_chunk[t];
    s[t] = v;
    __syncthreads();
    #pragma unroll
    for (int o = 1; o < NCHUNK; o <<= 1) {
        uint32_t u = (t >= o) ? s[t - o] : 0u;
        __syncthreads();
        s[t] += u;
        __syncthreads();
    }
    g_chunk[t] = s[t] - v;
}

// ---- K4: scatter sorted point records (coords + original idx) ----
__global__ void k_scatter(const float* __restrict__ x, int B) {
    int b = blockIdx.x * blockDim.x + threadIdx.x;
    if (b >= B) return;
    const float p0 = x[3 * b + 0];
    const float p1 = x[3 * b + 1];
    const float p2 = x[3 * b + 2];
    const uint32_t m = morton64(p0, p1, p2);
    const uint32_t pos = g_chunk[m >> 10] + atomicAdd(&g_hist[m], 1u);
    g_pts[pos] = make_float4(p0, p1, p2, __uint_as_float((uint32_t)b));
}

// ---- predicated loads (no branch divergence; ptxas would emit BSSY/BSYNC
//      for a C++ if/else, these stay straight-line) ----
__device__ __forceinline__ void pld128(float4& v, const float4* p, uint32_t en) {
    asm("{\n\t.reg .pred p;\n\tsetp.ne.u32 p, %5, 0;\n\t"
        "@p ld.global.nc.v4.f32 {%0,%1,%2,%3}, [%4];\n\t}"
        : "=f"(v.x), "=f"(v.y), "=f"(v.z), "=f"(v.w)
        : "l"(p), "r"(en));
}
__device__ __forceinline__ void pld64(float2& v, const float2* p, uint32_t en) {
    asm("{\n\t.reg .pred p;\n\tsetp.ne.u32 p, %3, 0;\n\t"
        "@p ld.global.nc.v2.f32 {%0,%1}, [%2];\n\t}"
        : "=f"(v.x), "=f"(v.y)
        : "l"(p), "r"(en));
}

// One x-pair: corners hA (x=i0) and hB (x=i0+1) with weights wA, wB.
// If i0 even, hB == hA^1 and both live in the aligned float4 at hA>>1
// (PRIME_X == 1) -> one LDG.128 instead of two LDG.64.
__device__ __forceinline__ void pair_accum(
    const float2* __restrict__ tab, const float4* __restrict__ tab4,
    uint32_t hA, uint32_t hB, uint32_t odd,
    float wA, float wB, float& a0, float& a1)
{
    float4 q;           // valid on even lanes
    float2 sA, sB;      // valid on odd lanes
    pld128(q, tab4 + (hA >> 1), odd ^ 1u);
    pld64(sA, tab + hA, odd);
    pld64(sB, tab + hB, odd);

    const bool hi = (hA & 1u) != 0u;   // position of corner A within the pair
    const float wlo = hi ? wB : wA;
    const float whi = hi ? wA : wB;

    const float c0e = fmaf(wlo, q.x, whi * q.z);
    const float c1e = fmaf(wlo, q.y, whi * q.w);
    const float c0o = fmaf(wA, sA.x, wB * sB.x);
    const float c1o = fmaf(wA, sA.y, wB * sB.y);

    a0 += odd ? c0o : c0e;
    a1 += odd ? c1o : c1e;
}

__device__ __forceinline__ void level_gather(
    float p0, float p1, float p2, int R, const float2* __restrict__ tab,
    float& a0, float& a1)
{
    const float scale = 0.5f * (float)R;
    const float r0 = (p0 + 1.0f) * scale;
    const float r1 = (p1 + 1.0f) * scale;
    const float r2 = (p2 + 1.0f) * scale;

    float f0 = floorf(r0);
    float f1 = floorf(r1);
    float f2 = floorf(r2);
    const float rmax = (float)(R - 1);
    f0 = fminf(fmaxf(f0, 0.0f), rmax);
    f1 = fminf(fmaxf(f1, 0.0f), rmax);
    f2 = fminf(fmaxf(f2, 0.0f), rmax);

    const float w0 = r0 - f0, w1 = r1 - f1, w2 = r2 - f2;
    const float u0 = 1.0f - w0, u1 = 1.0f - w1, u2 = 1.0f - w2;

    const uint32_t i0 = (uint32_t)f0;
    const uint32_t i1 = (uint32_t)f1;
    const uint32_t i2 = (uint32_t)f2;
    const uint32_t odd = i0 & 1u;

    const uint32_t xa = i0;
    const uint32_t xb = i0 + 1u;
    const uint32_t ya = i1 * PRIME_Y;
    const uint32_t yb = ya + PRIME_Y;
    const uint32_t za = i2 * PRIME_Z;
    const uint32_t zb = za + PRIME_Z;

    const uint32_t n00 = ya ^ za;
    const uint32_t n10 = yb ^ za;
    const uint32_t n01 = ya ^ zb;
    const uint32_t n11 = yb ^ zb;

    const float s00 = u1 * u2, s10 = w1 * u2, s01 = u1 * w2, s11 = w1 * w2;

    const float4* __restrict__ tab4 = reinterpret_cast<const float4*>(tab);

    a0 = 0.0f; a1 = 0.0f;
    pair_accum(tab, tab4, (xa ^ n00) & TMASK, (xb ^ n00) & TMASK, odd,
               u0 * s00, w0 * s00, a0, a1);
    pair_accum(tab, tab4, (xa ^ n10) & TMASK, (xb ^ n10) & TMASK, odd,
               u0 * s10, w0 * s10, a0, a1);
    pair_accum(tab, tab4, (xa ^ n01) & TMASK, (xb ^ n01) & TMASK, odd,
               u0 * s01, w0 * s01, a0, a1);
    pair_accum(tab, tab4, (xa ^ n11) & TMASK, (xb ^ n11) & TMASK, odd,
               u0 * s11, w0 * s11, a0, a1);
}

// ---- K5: main gather over morton-sorted point records ----
__global__ __launch_bounds__(256, 2) void hash_embed_kernel(
    const float* __restrict__ emb,
    float* __restrict__ out,
    int B)
{
    int b = blockIdx.x * blockDim.x + threadIdx.x;
    if (b >= B) return;

    const float4 pt = g_pts[b];                  // coalesced
    const float p0 = pt.x, p1 = pt.y, p2 = pt.z;
    const uint32_t idx = __float_as_uint(pt.w);

    float4* __restrict__ o = reinterpret_cast<float4*>(out) + (size_t)idx * 8;

    #pragma unroll 1
    for (int g = 0; g < NLVL / 2; ++g) {
        const int l0 = 2 * g;
        const int R0 = c_res[l0];
        const int R1 = c_res[l0 + 1];
        const float2* __restrict__ tab0 =
            reinterpret_cast<const float2*>(emb) + (size_t)l0 * TSZ;
        const float2* __restrict__ tab1 = tab0 + TSZ;

        float a0, a1, a2, a3;
        level_gather(p0, p1, p2, R0, tab0, a0, a1);
        level_gather(p0, p1, p2, R1, tab1, a2, a3);

        o[g] = make_float4(a0, a1, a2, a3);
    }
}

extern "C" void kernel_launch(void* const* d_in, const int* in_sizes, int n_in,
                              void* d_out, int out_size)
{
    const float* x   = (const float*)d_in[0];   // (B, 3) f32
    const float* emb = (const float*)d_in[1];   // (16, 2^19, 2) f32
    float* out = (float*)d_out;                 // (B, 32) f32

    const int B = in_sizes[0] / 3;
    const int threads = 256;
    const int blocks = (B + threads - 1) / threads;

    void* hist_ptr = nullptr;
    cudaGetSymbolAddress(&hist_ptr, g_hist);
    cudaMemsetAsync(hist_ptr, 0, NBINS * sizeof(uint32_t));

    k_hist<<<blocks, threads>>>(x, B);
    k_scan_chunks<<<NCHUNK, 1024>>>();
    k_scan_top<<<1, NCHUNK>>>();
    k_scatter<<<blocks, threads>>>(x, B);
    hash_embed_kernel<<<blocks, threads>>>(emb, out, B);
}

// round 6
// speedup vs baseline: 1.0629x; 1.0629x over previous
#include <cuda_runtime.h>
#include <cstdint>

#define NLVL 16
#define TSZ (1 << 19)
#define TMASK ((1u << 19) - 1u)
#define PRIME_Y 2654435761u
#define PRIME_Z 805459861u

#define BMAX (1 << 20)          // BSZ = 1048576
#define NBINS (1 << 18)         // 64^3 morton bins
#define NCHUNK (NBINS / 1024)   // 256

// ---- scratch (device globals; no allocation allowed) ----
__device__ uint32_t g_hist[NBINS];   // histogram -> scanned offsets -> cursors
__device__ uint32_t g_chunk[NCHUNK]; // chunk totals -> exclusive scanned
__device__ float4   g_pts[BMAX];     // sorted (p0,p1,p2, bitcast(orig idx))

// floor(16 * 2^(i/3)); ambiguous i=3,6,9,12,15 -> power-of-two branch
// (validated rel_err 3.9e-8).
__constant__ int c_res[NLVL] = {16, 20, 25, 32, 40, 50, 64, 80,
                                101, 128, 161, 203, 256, 322, 406, 512};

__device__ __forceinline__ uint32_t spread3(uint32_t v) {
    v &= 0x3FFu;
    v = (v | (v << 16)) & 0x030000FFu;
    v = (v | (v << 8))  & 0x0300F00Fu;
    v = (v | (v << 4))  & 0x030C30C3u;
    v = (v | (v << 2))  & 0x09249249u;
    return v;
}

__device__ __forceinline__ uint32_t morton64(float p0, float p1, float p2) {
    uint32_t c0 = (uint32_t)fminf(fmaxf(floorf((p0 + 1.0f) * 32.0f), 0.0f), 63.0f);
    uint32_t c1 = (uint32_t)fminf(fmaxf(floorf((p1 + 1.0f) * 32.0f), 0.0f), 63.0f);
    uint32_t c2 = (uint32_t)fminf(fmaxf(floorf((p2 + 1.0f) * 32.0f), 0.0f), 63.0f);
    return spread3(c0) | (spread3(c1) << 1) | (spread3(c2) << 2);
}

// ---- K1: histogram ----
__global__ void k_hist(const float* __restrict__ x, int B) {
    int b = blockIdx.x * blockDim.x + threadIdx.x;
    if (b >= B) return;
    atomicAdd(&g_hist[morton64(x[3 * b], x[3 * b + 1], x[3 * b + 2])], 1u);
}

// ---- K2: per-1024-bin chunk exclusive scan (in place) + chunk totals ----
__global__ void k_scan_chunks() {
    __shared__ uint32_t s[1024];
    const int t = threadIdx.x;
    const int base = blockIdx.x * 1024;
    const uint32_t v = g_hist[base + t];
    s[t] = v;
    __syncthreads();
    #pragma unroll
    for (int o = 1; o < 1024; o <<= 1) {
        uint32_t u = (t >= o) ? s[t - o] : 0u;
        __syncthreads();
        s[t] += u;
        __syncthreads();
    }
    g_hist[base + t] = s[t] - v;                 // exclusive within chunk
    if (t == 1023) g_chunk[blockIdx.x] = s[1023];
}

// ---- K3: exclusive scan of the 256 chunk totals ----
__global__ void k_scan_top() {
    __shared__ uint32_t s[NCHUNK];
    const int t = threadIdx.x;
    const uint32_t v = g_chunk[t];
    s[t] = v;
    __syncthreads();
    #pragma unroll
    for (int o = 1; o < NCHUNK; o <<= 1) {
        uint32_t u = (t >= o) ? s[t - o] : 0u;
        __syncthreads();
        s[t] += u;
        __syncthreads();
    }
    g_chunk[t] = s[t] - v;
}

// ---- K4: scatter sorted point records (coords + original idx) ----
__global__ void k_scatter(const float* __restrict__ x, int B) {
    int b = blockIdx.x * blockDim.x + threadIdx.x;
    if (b >= B) return;
    const float p0 = x[3 * b + 0];
    const float p1 = x[3 * b + 1];
    const float p2 = x[3 * b + 2];
    const uint32_t m = morton64(p0, p1, p2);
    const uint32_t pos = g_chunk[m >> 10] + atomicAdd(&g_hist[m], 1u);
    g_pts[pos] = make_float4(p0, p1, p2, __uint_as_float((uint32_t)b));
}

// ---- gather: one level, plain 8x LDG.64 (round-3 form; the round-4
//      predicated pair-merge regressed: 3 load instrs + replay overhead
//      beat the wavefront savings) ----
__device__ __forceinline__ void level_gather(
    float p0, float p1, float p2, int R, const float2* __restrict__ tab,
    float& a0, float& a1)
{
    const float scale = 0.5f * (float)R;
    const float r0 = (p0 + 1.0f) * scale;
    const float r1 = (p1 + 1.0f) * scale;
    const float r2 = (p2 + 1.0f) * scale;

    float f0 = floorf(r0);
    float f1 = floorf(r1);
    float f2 = floorf(r2);
    const float rmax = (float)(R - 1);
    f0 = fminf(fmaxf(f0, 0.0f), rmax);
    f1 = fminf(fmaxf(f1, 0.0f), rmax);
    f2 = fminf(fmaxf(f2, 0.0f), rmax);

    const float w0 = r0 - f0, w1 = r1 - f1, w2 = r2 - f2;
    const float u0 = 1.0f - w0, u1 = 1.0f - w1, u2 = 1.0f - w2;

    const uint32_t i0 = (uint32_t)f0;
    const uint32_t i1 = (uint32_t)f1;
    const uint32_t i2 = (uint32_t)f2;

    const uint32_t xa = i0;
    const uint32_t xb = i0 + 1u;
    const uint32_t ya = i1 * PRIME_Y;
    const uint32_t yb = ya + PRIME_Y;
    const uint32_t za = i2 * PRIME_Z;
    const uint32_t zb = za + PRIME_Z;

    const float2 v000 = __ldg(&tab[(xa ^ ya ^ za) & TMASK]);
    const float2 v100 = __ldg(&tab[(xb ^ ya ^ za) & TMASK]);
    const float2 v010 = __ldg(&tab[(xa ^ yb ^ za) & TMASK]);
    const float2 v110 = __ldg(&tab[(xb ^ yb ^ za) & TMASK]);
    const float2 v001 = __ldg(&tab[(xa ^ ya ^ zb) & TMASK]);
    const float2 v101 = __ldg(&tab[(xb ^ ya ^ zb) & TMASK]);
    const float2 v011 = __ldg(&tab[(xa ^ yb ^ zb) & TMASK]);
    const float2 v111 = __ldg(&tab[(xb ^ yb ^ zb) & TMASK]);

    const float w000 = u0 * u1 * u2;
    const float w100 = w0 * u1 * u2;
    const float w010 = u0 * w1 * u2;
    const float w110 = w0 * w1 * u2;
    const float w001 = u0 * u1 * w2;
    const float w101 = w0 * u1 * w2;
    const float w011 = u0 * w1 * w2;
    const float w111 = w0 * w1 * w2;

    a0 = w000 * v000.x;
    a1 = w000 * v000.y;
    a0 = fmaf(w100, v100.x, a0);  a1 = fmaf(w100, v100.y, a1);
    a0 = fmaf(w010, v010.x, a0);  a1 = fmaf(w010, v010.y, a1);
    a0 = fmaf(w110, v110.x, a0);  a1 = fmaf(w110, v110.y, a1);
    a0 = fmaf(w001, v001.x, a0);  a1 = fmaf(w001, v001.y, a1);
    a0 = fmaf(w101, v101.x, a0);  a1 = fmaf(w101, v101.y, a1);
    a0 = fmaf(w011, v011.x, a0);  a1 = fmaf(w011, v011.y, a1);
    a0 = fmaf(w111, v111.x, a0);  a1 = fmaf(w111, v111.y, a1);
}

// ---- K5: main gather over morton-sorted point records ----
__global__ __launch_bounds__(256, 3) void hash_embed_kernel(
    const float* __restrict__ emb,
    float* __restrict__ out,
    int B)
{
    int b = blockIdx.x * blockDim.x + threadIdx.x;
    if (b >= B) return;

    const float4 pt = __ldg(&g_pts[b]);          // fully coalesced point read
    const float p0 = pt.x, p1 = pt.y, p2 = pt.z;
    const uint32_t idx = __float_as_uint(pt.w);

    float4* __restrict__ o = reinterpret_cast<float4*>(out) + (size_t)idx * 8;

    #pragma unroll 1
    for (int g = 0; g < NLVL / 2; ++g) {
        const int l0 = 2 * g;
        const int R0 = c_res[l0];
        const int R1 = c_res[l0 + 1];
        const float2* __restrict__ tab0 =
            reinterpret_cast<const float2*>(emb) + (size_t)l0 * TSZ;
        const float2* __restrict__ tab1 = tab0 + TSZ;

        float a0, a1, a2, a3;
        level_gather(p0, p1, p2, R0, tab0, a0, a1);
        level_gather(p0, p1, p2, R1, tab1, a2, a3);

        // streaming store: evict-first so the 128MB output stream doesn't
        // thrash the 64MB table's L2 residency
        __stcs(&o[g], make_float4(a0, a1, a2, a3));
    }
}

extern "C" void kernel_launch(void* const* d_in, const int* in_sizes, int n_in,
                              void* d_out, int out_size)
{
    const float* x   = (const float*)d_in[0];   // (B, 3) f32
    const float* emb = (const float*)d_in[1];   // (16, 2^19, 2) f32
    float* out = (float*)d_out;                 // (B, 32) f32

    const int B = in_sizes[0] / 3;
    const int threads = 256;
    const int blocks = (B + threads - 1) / threads;

    void* hist_ptr = nullptr;
    cudaGetSymbolAddress(&hist_ptr, g_hist);
    cudaMemsetAsync(hist_ptr, 0, NBINS * sizeof(uint32_t));

    k_hist<<<blocks, threads>>>(x, B);
    k_scan_chunks<<<NCHUNK, 1024>>>();
    k_scan_top<<<1, NCHUNK>>>();
    k_scatter<<<blocks, threads>>>(x, B);
    hash_embed_kernel<<<blocks, threads>>>(emb, out, B);
}